// round 6
// baseline (speedup 1.0000x reference)
#include <cuda_runtime.h>
#include <cstdint>

#define NPv 50000
#define NAv 50000
#define Dv  128
#define Emax 800000
#define NBUCK_MAX 800   // (50000+63)/64 = 782

// ---------------- scratch ----------------
__device__ float g_agg1[(size_t)NPv * Dv];
__device__ float g_agg2[(size_t)NPv * Dv];
__device__ float g_agg3[(size_t)NAv * Dv];
__device__ float g_z1[(size_t)NPv * Dv];
__device__ float g_z2[(size_t)NPv * Dv];
__device__ float g_z3[(size_t)NAv * Dv];
__device__ float g_deg[6 * 50000];
__device__ float g_stats[7 * 128];
__device__ float g_wsum[2];
__device__ float g_beta[2];
__device__ float g_scale_p[128], g_shift_p[128];
__device__ float g_scale_a[128], g_shift_a[128];
__device__ int2  g_ebuf[3][Emax];
__device__ int   g_bstart[3][NBUCK_MAX + 1];
__device__ int   g_offs[3][NBUCK_MAX];

// ---------------- tf32 helpers ----------------
__device__ __forceinline__ uint32_t cvt_tf32(float x) {
    uint32_t r;
    asm("cvt.rna.tf32.f32 %0, %1;" : "=r"(r) : "f"(x));
    return r;
}
__device__ __forceinline__ void mma_tf32(float4& d, const uint32_t a[4],
                                         uint32_t b0, uint32_t b1) {
    asm volatile(
        "mma.sync.aligned.m16n8k8.row.col.f32.tf32.tf32.f32 "
        "{%0,%1,%2,%3},{%4,%5,%6,%7},{%8,%9},{%0,%1,%2,%3};"
        : "+f"(d.x), "+f"(d.y), "+f"(d.z), "+f"(d.w)
        : "r"(a[0]), "r"(a[1]), "r"(a[2]), "r"(a[3]), "r"(b0), "r"(b1));
}

// ---------------- zero scratch (deg/stats/wsum only; agg written fully) ------
__global__ void zero_kernel() {
    int i = blockIdx.x * blockDim.x + threadIdx.x;
    float4 z = make_float4(0.f, 0.f, 0.f, 0.f);
    if (i < (6 * 50000) / 4) ((float4*)g_deg)[i] = z;
    if (i < (7 * 128) / 4) ((float4*)g_stats)[i] = z;
    if (i < 2) g_wsum[i] = 0.f;
}

// ---------------- degrees ----------------
__global__ void degree_kernel(const int* __restrict__ s1, const int* __restrict__ d1,
                              const int* __restrict__ s2, const int* __restrict__ d2,
                              const int* __restrict__ s3, const int* __restrict__ d3,
                              int nE) {
    int i = blockIdx.x * blockDim.x + threadIdx.x;
    if (i >= nE) return;
    atomicAdd(&g_deg[0 * 50000 + s1[i]], 1.0f);
    atomicAdd(&g_deg[1 * 50000 + d1[i]], 1.0f);
    atomicAdd(&g_deg[2 * 50000 + s2[i]], 1.0f);
    atomicAdd(&g_deg[3 * 50000 + d2[i]], 1.0f);
    atomicAdd(&g_deg[4 * 50000 + s3[i]], 1.0f);
    atomicAdd(&g_deg[5 * 50000 + d3[i]], 1.0f);
}

__global__ void rsqrt_deg_kernel(int n) {
    int i = blockIdx.x * blockDim.x + threadIdx.x;
    if (i < n) g_deg[i] = rsqrtf(fmaxf(g_deg[i], 1.0f));
}

// ---------------- bucket prefix: counts from raw deg_in, exclusive scan ------
__global__ __launch_bounds__(256) void bucket_prefix_kernel(int MP, int MA) {
    int r = blockIdx.x;
    int M = (r == 2) ? MA : MP;
    int nb = (M + 63) >> 6;
    const float* degraw = g_deg + (2 * r + 1) * 50000;
    __shared__ int cnt[NBUCK_MAX];
    __shared__ int scan[256];
    int t = threadIdx.x;
    for (int b = t; b < nb; b += 256) {
        int base = b << 6;
        int n = min(64, M - base);
        float s = 0.f;
        for (int i = 0; i < n; i++) s += degraw[base + i];
        cnt[b] = (int)(s + 0.5f);
    }
    __syncthreads();
    // 4 contiguous buckets per thread
    int g0 = t * 4;
    int loc[4];
    int s = 0;
#pragma unroll
    for (int j = 0; j < 4; j++) {
        loc[j] = s;
        int b = g0 + j;
        s += (b < nb) ? cnt[b] : 0;
    }
    scan[t] = s;
    __syncthreads();
    for (int off = 1; off < 256; off <<= 1) {
        int v = (t >= off) ? scan[t - off] : 0;
        __syncthreads();
        scan[t] += v;
        __syncthreads();
    }
    int excl = scan[t] - s;
#pragma unroll
    for (int j = 0; j < 4; j++) {
        int b = g0 + j;
        if (b < nb) {
            int v = excl + loc[j];
            g_bstart[r][b] = v;
            g_offs[r][b] = v;
        }
    }
    if (t == 255) g_bstart[r][nb] = scan[255];
}

// ---------------- fill: bucketed edge lists ----------------
__global__ void fill_kernel(const int* __restrict__ s1, const int* __restrict__ d1,
                            const int* __restrict__ s2, const int* __restrict__ d2,
                            const int* __restrict__ s3, const int* __restrict__ d3,
                            int nE) {
    int r = blockIdx.y;
    const int* src = r == 0 ? s1 : r == 1 ? s2 : s3;
    const int* dst = r == 0 ? d1 : r == 1 ? d2 : d3;
    int i = blockIdx.x * blockDim.x + threadIdx.x;
    if (i >= nE) return;
    int sV = src[i], dV = dst[i];
    int b = dV >> 6;
    int pos = atomicAdd(&g_offs[r][b], 1);
    g_ebuf[r][pos] = make_int2(sV, dV & 63);
}

// ---------------- scatter2: per-bucket smem accumulation ----------------
__global__ __launch_bounds__(256) void scatter2_kernel(
    const float* __restrict__ hp, const float* __restrict__ ha, int MP, int MA) {
    int r = blockIdx.y;
    int b = blockIdx.x;
    int M = (r == 2) ? MA : MP;
    int nb = (M + 63) >> 6;
    if (b >= nb) return;
    const float* H = (r == 1) ? hp : ha;
    const float* rs = g_deg + (2 * r) * 50000;
    float* agg = (r == 0) ? g_agg1 : (r == 1) ? g_agg2 : g_agg3;

    __shared__ float acc[64 * 128];   // 32 KB
    float4 z4 = make_float4(0.f, 0.f, 0.f, 0.f);
    for (int i = threadIdx.x; i < 64 * 32; i += 256) ((float4*)acc)[i] = z4;
    __syncthreads();

    int start = g_bstart[r][b], end = g_bstart[r][b + 1];
    int lane = threadIdx.x & 31, wid = threadIdx.x >> 5;
    const int2* eb = g_ebuf[r];

    for (int e0 = start + wid * 4; e0 < end; e0 += 32) {
        int n = min(4, end - e0);
        int2 ed[4];
#pragma unroll
        for (int j = 0; j < 4; j++) ed[j] = __ldg((const int2*)eb + min(e0 + j, end - 1));
        float sc[4];
#pragma unroll
        for (int j = 0; j < 4; j++) sc[j] = __ldg(rs + ed[j].x);
        float v[4][4];
#pragma unroll
        for (int j = 0; j < 4; j++) {
            const float* hr = H + (size_t)ed[j].x * 128 + lane;
            v[j][0] = __ldg(hr);
            v[j][1] = __ldg(hr + 32);
            v[j][2] = __ldg(hr + 64);
            v[j][3] = __ldg(hr + 96);
        }
#pragma unroll
        for (int j = 0; j < 4; j++) {
            if (j < n) {
                float* a = acc + ed[j].y * 128 + lane;   // bank = lane, conflict-free
                atomicAdd(a, v[j][0] * sc[j]);
                atomicAdd(a + 32, v[j][1] * sc[j]);
                atomicAdd(a + 64, v[j][2] * sc[j]);
                atomicAdd(a + 96, v[j][3] * sc[j]);
            }
        }
    }
    __syncthreads();

    int base = b << 6;
    int rows = min(64, M - base);
    for (int i = threadIdx.x; i < rows * 32; i += 256) {
        int row = i >> 5, q = i & 31;
        ((float4*)(agg + (size_t)(base + row) * 128))[q] = ((const float4*)(acc + row * 128))[q];
    }
}

// ============ TF32 GEMM core: block tile 128x128, 8 warps (4m x 2n) ==========
#define GEMM_PROLOGUE()                                                        \
    __shared__ float As[128][36];                                              \
    __shared__ float Ws[32][136];                                              \
    const int tid = threadIdx.x;                                               \
    const int wid = tid >> 5, lane = tid & 31;                                 \
    const int grp = lane >> 2, tig = lane & 3;                                 \
    const int rowBase = blockIdx.x * 128;                                      \
    const int rowOff = (wid & 3) * 32;                                         \
    const int colOff = (wid >> 2) * 64;                                        \
    float4 acc[2][8];                                                          \
    _Pragma("unroll") for (int ms = 0; ms < 2; ms++)                           \
        _Pragma("unroll") for (int ns = 0; ns < 8; ns++)                       \
            acc[ms][ns] = make_float4(0.f, 0.f, 0.f, 0.f);

#define LOAD_CHUNK(kc)                                                         \
    _Pragma("unroll") for (int j = 0; j < 4; j++) {                            \
        int i = tid + 256 * j;                                                 \
        int r = i >> 3, c4 = (i & 7) << 2;                                     \
        int gr = min(rowBase + r, M - 1);                                      \
        aPre[j] = *(const float4*)(A + (size_t)gr * 128 + (kc) * 32 + c4);     \
        int k = i >> 5, w4 = (i & 31) << 2;                                    \
        wPre[j] = *(const float4*)(W + (size_t)((kc) * 32 + k) * 128 + w4);    \
    }

#define STORE_CHUNK()                                                          \
    _Pragma("unroll") for (int j = 0; j < 4; j++) {                            \
        int i = tid + 256 * j;                                                 \
        int r = i >> 3, c4 = (i & 7) << 2;                                     \
        uint4 ta;                                                              \
        ta.x = cvt_tf32(aPre[j].x); ta.y = cvt_tf32(aPre[j].y);                \
        ta.z = cvt_tf32(aPre[j].z); ta.w = cvt_tf32(aPre[j].w);                \
        *(uint4*)&As[r][c4] = ta;                                              \
        int k = i >> 5, w4 = (i & 31) << 2;                                    \
        uint4 tw;                                                              \
        tw.x = cvt_tf32(wPre[j].x); tw.y = cvt_tf32(wPre[j].y);                \
        tw.z = cvt_tf32(wPre[j].z); tw.w = cvt_tf32(wPre[j].w);                \
        *(uint4*)&Ws[k][w4] = tw;                                              \
    }

#define MMA_CHUNK()                                                            \
    _Pragma("unroll") for (int ks = 0; ks < 4; ks++) {                         \
        int k0 = ks * 8;                                                       \
        uint32_t a[2][4];                                                      \
        _Pragma("unroll") for (int ms = 0; ms < 2; ms++) {                     \
            int r = rowOff + ms * 16 + grp;                                    \
            a[ms][0] = __float_as_uint(As[r][k0 + tig]);                       \
            a[ms][1] = __float_as_uint(As[r + 8][k0 + tig]);                   \
            a[ms][2] = __float_as_uint(As[r][k0 + tig + 4]);                   \
            a[ms][3] = __float_as_uint(As[r + 8][k0 + tig + 4]);               \
        }                                                                      \
        _Pragma("unroll") for (int ns = 0; ns < 8; ns++) {                     \
            int cn = colOff + ns * 8 + grp;                                    \
            uint32_t b0 = __float_as_uint(Ws[k0 + tig][cn]);                   \
            uint32_t b1 = __float_as_uint(Ws[k0 + tig + 4][cn]);               \
            mma_tf32(acc[0][ns], a[0], b0, b1);                                \
            mma_tf32(acc[1][ns], a[1], b0, b1);                                \
        }                                                                      \
    }

#define GEMM_MAINLOOP()                                                        \
    float4 aPre[4], wPre[4];                                                   \
    LOAD_CHUNK(0)                                                              \
    _Pragma("unroll") for (int kc = 0; kc < 4; kc++) {                         \
        if (kc > 0) __syncthreads();                                           \
        STORE_CHUNK()                                                          \
        __syncthreads();                                                       \
        if (kc < 3) { LOAD_CHUNK(kc + 1) }                                     \
        MMA_CHUNK()                                                            \
    }

__global__ __launch_bounds__(256, 2) void conv_gemm_tf32(
    const float* __restrict__ A1, const float* __restrict__ A2, const float* __restrict__ A3,
    const float* __restrict__ W1, const float* __restrict__ W2, const float* __restrict__ W3,
    const float* __restrict__ rs1, const float* __restrict__ rs2, const float* __restrict__ rs3,
    float* __restrict__ C1, float* __restrict__ C2, float* __restrict__ C3, int M) {
    const int rel = blockIdx.y;
    const float* A = rel == 0 ? A1 : rel == 1 ? A2 : A3;
    const float* W = rel == 0 ? W1 : rel == 1 ? W2 : W3;
    const float* rs = rel == 0 ? rs1 : rel == 1 ? rs2 : rs3;
    float* C = rel == 0 ? C1 : rel == 1 ? C2 : C3;

    GEMM_PROLOGUE()
    GEMM_MAINLOOP()

#pragma unroll
    for (int ms = 0; ms < 2; ms++) {
        int rA = rowBase + rowOff + ms * 16 + grp;
        int rB = rA + 8;
        float sA = (rA < M) ? rs[rA] : 0.f;
        float sB = (rB < M) ? rs[rB] : 0.f;
#pragma unroll
        for (int ns = 0; ns < 8; ns++) {
            int cC = colOff + ns * 8 + 2 * tig;
            if (rA < M) {
                float2 o = make_float2(acc[ms][ns].x * sA, acc[ms][ns].y * sA);
                *(float2*)(C + (size_t)rA * 128 + cC) = o;
            }
            if (rB < M) {
                float2 o = make_float2(acc[ms][ns].z * sB, acc[ms][ns].w * sB);
                *(float2*)(C + (size_t)rB * 128 + cC) = o;
            }
        }
    }
}

__global__ __launch_bounds__(256, 2) void att_gemm_tf32(
    const float* __restrict__ Z1, const float* __restrict__ Z2,
    const float* __restrict__ W,
    const float* __restrict__ bb, const float* __restrict__ qq,
    float* __restrict__ wsum, int M) {
    const float* A = blockIdx.y == 0 ? Z1 : Z2;

    GEMM_PROLOGUE()
    GEMM_MAINLOOP()

    float p = 0.f;
#pragma unroll
    for (int ms = 0; ms < 2; ms++) {
        int rA = rowBase + rowOff + ms * 16 + grp;
        int rB = rA + 8;
#pragma unroll
        for (int ns = 0; ns < 8; ns++) {
            int cC = colOff + ns * 8 + 2 * tig;
            float b0v = __ldg(bb + cC), b1v = __ldg(bb + cC + 1);
            float q0v = __ldg(qq + cC), q1v = __ldg(qq + cC + 1);
            if (rA < M)
                p += tanhf(acc[ms][ns].x + b0v) * q0v + tanhf(acc[ms][ns].y + b1v) * q1v;
            if (rB < M)
                p += tanhf(acc[ms][ns].z + b0v) * q0v + tanhf(acc[ms][ns].w + b1v) * q1v;
        }
    }
#pragma unroll
    for (int o = 16; o > 0; o >>= 1) p += __shfl_xor_sync(0xffffffffu, p, o);
    if (lane == 0) atomicAdd(wsum + blockIdx.y, p);
}

// ---------------- column moments ----------------
__global__ __launch_bounds__(128) void stats_paper_kernel(
    const float* __restrict__ z1, const float* __restrict__ z2, int M) {
    int c = threadIdx.x;
    int r0 = blockIdx.x * 128;
    int r1 = min(r0 + 128, M);
    float s1 = 0.f, s2 = 0.f, q1 = 0.f, q2 = 0.f, cx = 0.f;
    for (int r = r0; r < r1; r++) {
        float v1 = z1[(size_t)r * 128 + c];
        float v2 = z2[(size_t)r * 128 + c];
        s1 += v1; s2 += v2; q1 += v1 * v1; q2 += v2 * v2; cx += v1 * v2;
    }
    atomicAdd(&g_stats[0 * 128 + c], s1);
    atomicAdd(&g_stats[1 * 128 + c], s2);
    atomicAdd(&g_stats[2 * 128 + c], q1);
    atomicAdd(&g_stats[3 * 128 + c], q2);
    atomicAdd(&g_stats[4 * 128 + c], cx);
}

__global__ __launch_bounds__(128) void stats_author_kernel(const float* __restrict__ z3, int M) {
    int c = threadIdx.x;
    int r0 = blockIdx.x * 128;
    int r1 = min(r0 + 128, M);
    float s3 = 0.f, q3 = 0.f;
    for (int r = r0; r < r1; r++) {
        float v = z3[(size_t)r * 128 + c];
        s3 += v; q3 += v * v;
    }
    atomicAdd(&g_stats[5 * 128 + c], s3);
    atomicAdd(&g_stats[6 * 128 + c], q3);
}

// ---------------- finalize ----------------
__global__ void finalize_kernel(const float* __restrict__ gamma, const float* __restrict__ betaBN,
                                int MP, int MA) {
    int j = threadIdx.x;
    float w1 = g_wsum[0] / (float)MP;
    float w2 = g_wsum[1] / (float)MP;
    float m = fmaxf(w1, w2);
    float e1 = expf(w1 - m), e2 = expf(w2 - m);
    float b1 = e1 / (e1 + e2), b2 = e2 / (e1 + e2);
    if (j == 0) { g_beta[0] = b1; g_beta[1] = b2; }

    float S1 = g_stats[0 * 128 + j], S2 = g_stats[1 * 128 + j];
    float Q1 = g_stats[2 * 128 + j], Q2 = g_stats[3 * 128 + j];
    float CX = g_stats[4 * 128 + j];
    float S3 = g_stats[5 * 128 + j], Q3 = g_stats[6 * 128 + j];

    float invMP = 1.0f / (float)MP;
    float mu = (b1 * S1 + b2 * S2) * invMP;
    float ex2 = (b1 * b1 * Q1 + 2.f * b1 * b2 * CX + b2 * b2 * Q2) * invMP;
    float var = ex2 - mu * mu;
    float sc = gamma[j] * rsqrtf(var + 1e-5f);
    g_scale_p[j] = sc;
    g_shift_p[j] = betaBN[j] - mu * sc;

    float invMA = 1.0f / (float)MA;
    float mua = S3 * invMA;
    float vara = Q3 * invMA - mua * mua;
    float sca = gamma[j] * rsqrtf(vara + 1e-5f);
    g_scale_a[j] = sca;
    g_shift_a[j] = betaBN[j] - mua * sca;
}

// ---------------- combine + BN + row L2 normalize ----------------
__global__ __launch_bounds__(256) void out_paper_kernel(
    const float* __restrict__ z1, const float* __restrict__ z2,
    float* __restrict__ out, int M) {
    int gt = blockIdx.x * blockDim.x + threadIdx.x;
    int row = gt >> 5, lane = gt & 31;
    if (row >= M) return;
    float b1 = g_beta[0], b2 = g_beta[1];
    float4 v1 = *((const float4*)(z1 + (size_t)row * 128) + lane);
    float4 v2 = *((const float4*)(z2 + (size_t)row * 128) + lane);
    float4 sc = *(const float4*)&g_scale_p[lane * 4];
    float4 sh = *(const float4*)&g_shift_p[lane * 4];
    float4 y;
    y.x = (b1 * v1.x + b2 * v2.x) * sc.x + sh.x;
    y.y = (b1 * v1.y + b2 * v2.y) * sc.y + sh.y;
    y.z = (b1 * v1.z + b2 * v2.z) * sc.z + sh.z;
    y.w = (b1 * v1.w + b2 * v2.w) * sc.w + sh.w;
    float ss = y.x * y.x + y.y * y.y + y.z * y.z + y.w * y.w;
#pragma unroll
    for (int o = 16; o > 0; o >>= 1) ss += __shfl_xor_sync(0xffffffffu, ss, o);
    float inv = rsqrtf(ss + 1e-12f);
    float4 o4 = make_float4(y.x * inv, y.y * inv, y.z * inv, y.w * inv);
    *((float4*)(out + (size_t)row * 128) + lane) = o4;
}

__global__ __launch_bounds__(256) void out_author_kernel(
    const float* __restrict__ z3, float* __restrict__ out, int M) {
    int gt = blockIdx.x * blockDim.x + threadIdx.x;
    int row = gt >> 5, lane = gt & 31;
    if (row >= M) return;
    float4 v = *((const float4*)(z3 + (size_t)row * 128) + lane);
    float4 sc = *(const float4*)&g_scale_a[lane * 4];
    float4 sh = *(const float4*)&g_shift_a[lane * 4];
    float4 y;
    y.x = v.x * sc.x + sh.x;
    y.y = v.y * sc.y + sh.y;
    y.z = v.z * sc.z + sh.z;
    y.w = v.w * sc.w + sh.w;
    float ss = y.x * y.x + y.y * y.y + y.z * y.z + y.w * y.w;
#pragma unroll
    for (int o = 16; o > 0; o >>= 1) ss += __shfl_xor_sync(0xffffffffu, ss, o);
    float inv = rsqrtf(ss + 1e-12f);
    float4 o4 = make_float4(y.x * inv, y.y * inv, y.z * inv, y.w * inv);
    *((float4*)(out + (size_t)row * 128) + lane) = o4;
}

// ---------------- launch ----------------
extern "C" void kernel_launch(void* const* d_in, const int* in_sizes, int n_in,
                              void* d_out, int out_size) {
    const float* h_paper  = (const float*)d_in[0];
    const float* h_author = (const float*)d_in[1];
    const float* W1   = (const float*)d_in[2];
    const float* W2   = (const float*)d_in[3];
    const float* W3   = (const float*)d_in[4];
    const float* attW = (const float*)d_in[5];
    const float* attb = (const float*)d_in[6];
    const float* attq = (const float*)d_in[7];
    const float* gamma  = (const float*)d_in[8];
    const float* betaBN = (const float*)d_in[9];
    const int* s1 = (const int*)d_in[10];
    const int* d1 = (const int*)d_in[11];
    const int* s2 = (const int*)d_in[12];
    const int* d2 = (const int*)d_in[13];
    const int* s3 = (const int*)d_in[14];
    const int* d3 = (const int*)d_in[15];
    float* out = (float*)d_out;

    const int MP = in_sizes[0] / Dv;
    const int MA = in_sizes[1] / Dv;
    const int E  = in_sizes[10];

    float *agg1, *agg2, *agg3, *z1, *z2, *z3, *deg, *wsum;
    cudaGetSymbolAddress((void**)&agg1, g_agg1);
    cudaGetSymbolAddress((void**)&agg2, g_agg2);
    cudaGetSymbolAddress((void**)&agg3, g_agg3);
    cudaGetSymbolAddress((void**)&z1, g_z1);
    cudaGetSymbolAddress((void**)&z2, g_z2);
    cudaGetSymbolAddress((void**)&z3, g_z3);
    cudaGetSymbolAddress((void**)&deg, g_deg);
    cudaGetSymbolAddress((void**)&wsum, g_wsum);

    // 1. zero deg/stats/wsum
    zero_kernel<<<(6 * 50000 / 4 + 255) / 256, 256>>>();
    // 2. degrees (raw counts)
    degree_kernel<<<(E + 255) / 256, 256>>>(s1, d1, s2, d2, s3, d3, E);
    // 3. bucket offsets from raw deg_in (must precede rsqrt)
    bucket_prefix_kernel<<<3, 256>>>(MP, MA);
    // 4. rsqrt degrees
    rsqrt_deg_kernel<<<(6 * 50000 + 255) / 256, 256>>>(6 * 50000);
    // 5. fill bucketed edge lists
    {
        dim3 g((E + 255) / 256, 3);
        fill_kernel<<<g, 256>>>(s1, d1, s2, d2, s3, d3, E);
    }
    // 6. bucketed scatter with smem accumulation
    {
        int nb = (MP + 63) >> 6;   // == (MA+63)>>6 here
        dim3 g(nb, 3);
        scatter2_kernel<<<g, 256>>>(h_paper, h_author, MP, MA);
    }
    // 7. conv GEMMs + attention GEMMs (tf32 tensor cores)
    {
        dim3 g((MP + 127) / 128, 3);
        conv_gemm_tf32<<<g, 256>>>(agg1, agg2, agg3, W1, W2, W3,
                                   deg + 1 * 50000, deg + 3 * 50000, deg + 5 * 50000,
                                   z1, z2, z3, MP);
        dim3 ga((MP + 127) / 128, 2);
        att_gemm_tf32<<<ga, 256>>>(z1, z2, attW, attb, attq, wsum, MP);
    }
    // 8. moments, finalize, outputs
    stats_paper_kernel<<<(MP + 127) / 128, 128>>>(z1, z2, MP);
    stats_author_kernel<<<(MA + 127) / 128, 128>>>(z3, MA);
    finalize_kernel<<<1, 128>>>(gamma, betaBN, MP, MA);
    out_paper_kernel<<<(MP * 32 + 255) / 256, 256>>>(z1, z2, out, MP);
    out_author_kernel<<<(MA * 32 + 255) / 256, 256>>>(z3, out + (size_t)MP * Dv, MA);
}

// round 7
// speedup vs baseline: 1.4118x; 1.4118x over previous
#include <cuda_runtime.h>
#include <cstdint>

#define NPv 50000
#define NAv 50000
#define Dv  128
#define Emax 800000

// ---------------- scratch ----------------
__device__ float g_agg1[(size_t)NPv * Dv];
__device__ float g_agg2[(size_t)NPv * Dv];
__device__ float g_agg3[(size_t)NAv * Dv];
__device__ float g_z1[(size_t)NPv * Dv];
__device__ float g_z2[(size_t)NPv * Dv];
__device__ float g_z3[(size_t)NAv * Dv];
__device__ float g_deg[6 * 50000];
__device__ float g_stats[7 * 128];
__device__ float g_wsum[2];
__device__ float g_beta[2];
__device__ float g_scale_p[128], g_shift_p[128];
__device__ float g_scale_a[128], g_shift_a[128];
__device__ int2  g_ebuf[3][Emax];
__device__ int   g_soffs[3][50000];

// ---------------- tf32 helpers ----------------
__device__ __forceinline__ uint32_t cvt_tf32(float x) {
    uint32_t r;
    asm("cvt.rna.tf32.f32 %0, %1;" : "=r"(r) : "f"(x));
    return r;
}
__device__ __forceinline__ void mma_tf32(float4& d, const uint32_t a[4],
                                         uint32_t b0, uint32_t b1) {
    asm volatile(
        "mma.sync.aligned.m16n8k8.row.col.f32.tf32.tf32.f32 "
        "{%0,%1,%2,%3},{%4,%5,%6,%7},{%8,%9},{%0,%1,%2,%3};"
        : "+f"(d.x), "+f"(d.y), "+f"(d.z), "+f"(d.w)
        : "r"(a[0]), "r"(a[1]), "r"(a[2]), "r"(a[3]), "r"(b0), "r"(b1));
}

// ---------------- zero scratch ----------------
__global__ void zero_kernel() {
    size_t i = (size_t)blockIdx.x * blockDim.x + threadIdx.x;   // float4 index
    size_t n4 = (size_t)NPv * Dv / 4;
    float4 z = make_float4(0.f, 0.f, 0.f, 0.f);
    if (i < n4) {
        ((float4*)g_agg1)[i] = z;
        ((float4*)g_agg2)[i] = z;
        ((float4*)g_agg3)[i] = z;
    }
    if (i < (6 * 50000) / 4) ((float4*)g_deg)[i] = z;
    if (i < (7 * 128) / 4) ((float4*)g_stats)[i] = z;
    if (i < 2) g_wsum[i] = 0.f;
}

// ---------------- degrees ----------------
__global__ void degree_kernel(const int* __restrict__ s1, const int* __restrict__ d1,
                              const int* __restrict__ s2, const int* __restrict__ d2,
                              const int* __restrict__ s3, const int* __restrict__ d3,
                              int nE) {
    int i = blockIdx.x * blockDim.x + threadIdx.x;
    if (i >= nE) return;
    atomicAdd(&g_deg[0 * 50000 + s1[i]], 1.0f);
    atomicAdd(&g_deg[1 * 50000 + d1[i]], 1.0f);
    atomicAdd(&g_deg[2 * 50000 + s2[i]], 1.0f);
    atomicAdd(&g_deg[3 * 50000 + d2[i]], 1.0f);
    atomicAdd(&g_deg[4 * 50000 + s3[i]], 1.0f);
    atomicAdd(&g_deg[5 * 50000 + d3[i]], 1.0f);
}

__global__ void rsqrt_deg_kernel(int n) {
    int i = blockIdx.x * blockDim.x + threadIdx.x;
    if (i < n) g_deg[i] = rsqrtf(fmaxf(g_deg[i], 1.0f));
}

// -------- src prefix: counting-sort offsets from raw deg_out ---------------
// grid = 3 (relation), block = 1024. Must run BEFORE rsqrt_deg.
__global__ __launch_bounds__(1024) void src_prefix_kernel(int M) {
    int r = blockIdx.x;
    const float* degraw = g_deg + (2 * r) * 50000;   // deg_out of relation r
    const int PT = (50000 + 1023) / 1024;            // 49
    int t = threadIdx.x;
    int base = t * PT;
    __shared__ int part[1024];
    int s = 0;
    for (int i = 0; i < PT; i++) {
        int n = base + i;
        if (n < M) s += (int)(degraw[n] + 0.5f);
    }
    part[t] = s;
    __syncthreads();
    for (int off = 1; off < 1024; off <<= 1) {
        int v = (t >= off) ? part[t - off] : 0;
        __syncthreads();
        part[t] += v;
        __syncthreads();
    }
    int run = part[t] - s;   // exclusive prefix of this thread's range
    for (int i = 0; i < PT; i++) {
        int n = base + i;
        if (n < M) {
            g_soffs[r][n] = run;
            run += (int)(degraw[n] + 0.5f);
        }
    }
}

// ---------------- fill: src-sorted edge lists ----------------
__global__ void fill_kernel(const int* __restrict__ s1, const int* __restrict__ d1,
                            const int* __restrict__ s2, const int* __restrict__ d2,
                            const int* __restrict__ s3, const int* __restrict__ d3,
                            int nE) {
    int r = blockIdx.y;
    const int* src = r == 0 ? s1 : r == 1 ? s2 : s3;
    const int* dst = r == 0 ? d1 : r == 1 ? d2 : d3;
    int i = blockIdx.x * blockDim.x + threadIdx.x;
    if (i >= nE) return;
    int sV = src[i], dV = dst[i];
    int pos = atomicAdd(&g_soffs[r][sV], 1);
    g_ebuf[r][pos] = make_int2(sV, dV);
}

// ------- scatter (src-sorted): agg[dst] += H[src]*rs_out[src], REDG.v4 -------
__global__ __launch_bounds__(256) void scatter_kernel(
    const float* __restrict__ H, const int2* __restrict__ eb,
    const float* __restrict__ rs_out, float* __restrict__ agg, int nE) {
    int warp = (blockIdx.x * blockDim.x + threadIdx.x) >> 5;
    int lane = threadIdx.x & 31;
    int e0 = warp << 2;
    if (e0 >= nE) return;

    int2 ed[4];
#pragma unroll
    for (int i = 0; i < 4; i++) ed[i] = __ldg(eb + min(e0 + i, nE - 1));
    float sc[4];
#pragma unroll
    for (int i = 0; i < 4; i++) sc[i] = __ldg(rs_out + ed[i].x);
    float4 v[4];
#pragma unroll
    for (int i = 0; i < 4; i++)
        v[i] = *((const float4*)(H + (size_t)ed[i].x * Dv) + lane);   // sorted: L1 hits

    int n = min(4, nE - e0);
#pragma unroll
    for (int i = 0; i < 4; i++) {
        if (i < n) {
            float4 u = v[i];
            float c = sc[i];
            u.x *= c; u.y *= c; u.z *= c; u.w *= c;
            float* p = agg + (size_t)ed[i].y * Dv + lane * 4;
            asm volatile("red.global.add.v4.f32 [%0], {%1,%2,%3,%4};"
                         :: "l"(p), "f"(u.x), "f"(u.y), "f"(u.z), "f"(u.w) : "memory");
        }
    }
}

// ============ TF32 GEMM core: block tile 128x128, 8 warps (4m x 2n) ==========
#define GEMM_PROLOGUE()                                                        \
    __shared__ float As[128][36];                                              \
    __shared__ float Ws[32][136];                                              \
    const int tid = threadIdx.x;                                               \
    const int wid = tid >> 5, lane = tid & 31;                                 \
    const int grp = lane >> 2, tig = lane & 3;                                 \
    const int rowBase = blockIdx.x * 128;                                      \
    const int rowOff = (wid & 3) * 32;                                         \
    const int colOff = (wid >> 2) * 64;                                        \
    float4 acc[2][8];                                                          \
    _Pragma("unroll") for (int ms = 0; ms < 2; ms++)                           \
        _Pragma("unroll") for (int ns = 0; ns < 8; ns++)                       \
            acc[ms][ns] = make_float4(0.f, 0.f, 0.f, 0.f);

#define LOAD_CHUNK(kc)                                                         \
    _Pragma("unroll") for (int j = 0; j < 4; j++) {                            \
        int i = tid + 256 * j;                                                 \
        int r = i >> 3, c4 = (i & 7) << 2;                                     \
        int gr = min(rowBase + r, M - 1);                                      \
        aPre[j] = *(const float4*)(A + (size_t)gr * 128 + (kc) * 32 + c4);     \
        int k = i >> 5, w4 = (i & 31) << 2;                                    \
        wPre[j] = *(const float4*)(W + (size_t)((kc) * 32 + k) * 128 + w4);    \
    }

#define STORE_CHUNK()                                                          \
    _Pragma("unroll") for (int j = 0; j < 4; j++) {                            \
        int i = tid + 256 * j;                                                 \
        int r = i >> 3, c4 = (i & 7) << 2;                                     \
        uint4 ta;                                                              \
        ta.x = cvt_tf32(aPre[j].x); ta.y = cvt_tf32(aPre[j].y);                \
        ta.z = cvt_tf32(aPre[j].z); ta.w = cvt_tf32(aPre[j].w);                \
        *(uint4*)&As[r][c4] = ta;                                              \
        int k = i >> 5, w4 = (i & 31) << 2;                                    \
        uint4 tw;                                                              \
        tw.x = cvt_tf32(wPre[j].x); tw.y = cvt_tf32(wPre[j].y);                \
        tw.z = cvt_tf32(wPre[j].z); tw.w = cvt_tf32(wPre[j].w);                \
        *(uint4*)&Ws[k][w4] = tw;                                              \
    }

#define MMA_CHUNK()                                                            \
    _Pragma("unroll") for (int ks = 0; ks < 4; ks++) {                         \
        int k0 = ks * 8;                                                       \
        uint32_t a[2][4];                                                      \
        _Pragma("unroll") for (int ms = 0; ms < 2; ms++) {                     \
            int r = rowOff + ms * 16 + grp;                                    \
            a[ms][0] = __float_as_uint(As[r][k0 + tig]);                       \
            a[ms][1] = __float_as_uint(As[r + 8][k0 + tig]);                   \
            a[ms][2] = __float_as_uint(As[r][k0 + tig + 4]);                   \
            a[ms][3] = __float_as_uint(As[r + 8][k0 + tig + 4]);               \
        }                                                                      \
        _Pragma("unroll") for (int ns = 0; ns < 8; ns++) {                     \
            int cn = colOff + ns * 8 + grp;                                    \
            uint32_t b0 = __float_as_uint(Ws[k0 + tig][cn]);                   \
            uint32_t b1 = __float_as_uint(Ws[k0 + tig + 4][cn]);               \
            mma_tf32(acc[0][ns], a[0], b0, b1);                                \
            mma_tf32(acc[1][ns], a[1], b0, b1);                                \
        }                                                                      \
    }

#define GEMM_MAINLOOP()                                                        \
    float4 aPre[4], wPre[4];                                                   \
    LOAD_CHUNK(0)                                                              \
    _Pragma("unroll") for (int kc = 0; kc < 4; kc++) {                         \
        if (kc > 0) __syncthreads();                                           \
        STORE_CHUNK()                                                          \
        __syncthreads();                                                       \
        if (kc < 3) { LOAD_CHUNK(kc + 1) }                                     \
        MMA_CHUNK()                                                            \
    }

__global__ __launch_bounds__(256, 2) void conv_gemm_tf32(
    const float* __restrict__ A1, const float* __restrict__ A2, const float* __restrict__ A3,
    const float* __restrict__ W1, const float* __restrict__ W2, const float* __restrict__ W3,
    const float* __restrict__ rs1, const float* __restrict__ rs2, const float* __restrict__ rs3,
    float* __restrict__ C1, float* __restrict__ C2, float* __restrict__ C3, int M) {
    const int rel = blockIdx.y;
    const float* A = rel == 0 ? A1 : rel == 1 ? A2 : A3;
    const float* W = rel == 0 ? W1 : rel == 1 ? W2 : W3;
    const float* rs = rel == 0 ? rs1 : rel == 1 ? rs2 : rs3;
    float* C = rel == 0 ? C1 : rel == 1 ? C2 : C3;

    GEMM_PROLOGUE()
    GEMM_MAINLOOP()

#pragma unroll
    for (int ms = 0; ms < 2; ms++) {
        int rA = rowBase + rowOff + ms * 16 + grp;
        int rB = rA + 8;
        float sA = (rA < M) ? rs[rA] : 0.f;
        float sB = (rB < M) ? rs[rB] : 0.f;
#pragma unroll
        for (int ns = 0; ns < 8; ns++) {
            int cC = colOff + ns * 8 + 2 * tig;
            if (rA < M) {
                float2 o = make_float2(acc[ms][ns].x * sA, acc[ms][ns].y * sA);
                *(float2*)(C + (size_t)rA * 128 + cC) = o;
            }
            if (rB < M) {
                float2 o = make_float2(acc[ms][ns].z * sB, acc[ms][ns].w * sB);
                *(float2*)(C + (size_t)rB * 128 + cC) = o;
            }
        }
    }
}

__global__ __launch_bounds__(256, 2) void att_gemm_tf32(
    const float* __restrict__ Z1, const float* __restrict__ Z2,
    const float* __restrict__ W,
    const float* __restrict__ bb, const float* __restrict__ qq,
    float* __restrict__ wsum, int M) {
    const float* A = blockIdx.y == 0 ? Z1 : Z2;

    GEMM_PROLOGUE()
    GEMM_MAINLOOP()

    float p = 0.f;
#pragma unroll
    for (int ms = 0; ms < 2; ms++) {
        int rA = rowBase + rowOff + ms * 16 + grp;
        int rB = rA + 8;
#pragma unroll
        for (int ns = 0; ns < 8; ns++) {
            int cC = colOff + ns * 8 + 2 * tig;
            float b0v = __ldg(bb + cC), b1v = __ldg(bb + cC + 1);
            float q0v = __ldg(qq + cC), q1v = __ldg(qq + cC + 1);
            if (rA < M)
                p += tanhf(acc[ms][ns].x + b0v) * q0v + tanhf(acc[ms][ns].y + b1v) * q1v;
            if (rB < M)
                p += tanhf(acc[ms][ns].z + b0v) * q0v + tanhf(acc[ms][ns].w + b1v) * q1v;
        }
    }
#pragma unroll
    for (int o = 16; o > 0; o >>= 1) p += __shfl_xor_sync(0xffffffffu, p, o);
    if (lane == 0) atomicAdd(wsum + blockIdx.y, p);
}

// ---------------- column moments ----------------
__global__ __launch_bounds__(128) void stats_paper_kernel(
    const float* __restrict__ z1, const float* __restrict__ z2, int M) {
    int c = threadIdx.x;
    int r0 = blockIdx.x * 128;
    int r1 = min(r0 + 128, M);
    float s1 = 0.f, s2 = 0.f, q1 = 0.f, q2 = 0.f, cx = 0.f;
    for (int r = r0; r < r1; r++) {
        float v1 = z1[(size_t)r * 128 + c];
        float v2 = z2[(size_t)r * 128 + c];
        s1 += v1; s2 += v2; q1 += v1 * v1; q2 += v2 * v2; cx += v1 * v2;
    }
    atomicAdd(&g_stats[0 * 128 + c], s1);
    atomicAdd(&g_stats[1 * 128 + c], s2);
    atomicAdd(&g_stats[2 * 128 + c], q1);
    atomicAdd(&g_stats[3 * 128 + c], q2);
    atomicAdd(&g_stats[4 * 128 + c], cx);
}

__global__ __launch_bounds__(128) void stats_author_kernel(const float* __restrict__ z3, int M) {
    int c = threadIdx.x;
    int r0 = blockIdx.x * 128;
    int r1 = min(r0 + 128, M);
    float s3 = 0.f, q3 = 0.f;
    for (int r = r0; r < r1; r++) {
        float v = z3[(size_t)r * 128 + c];
        s3 += v; q3 += v * v;
    }
    atomicAdd(&g_stats[5 * 128 + c], s3);
    atomicAdd(&g_stats[6 * 128 + c], q3);
}

// ---------------- finalize ----------------
__global__ void finalize_kernel(const float* __restrict__ gamma, const float* __restrict__ betaBN,
                                int MP, int MA) {
    int j = threadIdx.x;
    float w1 = g_wsum[0] / (float)MP;
    float w2 = g_wsum[1] / (float)MP;
    float m = fmaxf(w1, w2);
    float e1 = expf(w1 - m), e2 = expf(w2 - m);
    float b1 = e1 / (e1 + e2), b2 = e2 / (e1 + e2);
    if (j == 0) { g_beta[0] = b1; g_beta[1] = b2; }

    float S1 = g_stats[0 * 128 + j], S2 = g_stats[1 * 128 + j];
    float Q1 = g_stats[2 * 128 + j], Q2 = g_stats[3 * 128 + j];
    float CX = g_stats[4 * 128 + j];
    float S3 = g_stats[5 * 128 + j], Q3 = g_stats[6 * 128 + j];

    float invMP = 1.0f / (float)MP;
    float mu = (b1 * S1 + b2 * S2) * invMP;
    float ex2 = (b1 * b1 * Q1 + 2.f * b1 * b2 * CX + b2 * b2 * Q2) * invMP;
    float var = ex2 - mu * mu;
    float sc = gamma[j] * rsqrtf(var + 1e-5f);
    g_scale_p[j] = sc;
    g_shift_p[j] = betaBN[j] - mu * sc;

    float invMA = 1.0f / (float)MA;
    float mua = S3 * invMA;
    float vara = Q3 * invMA - mua * mua;
    float sca = gamma[j] * rsqrtf(vara + 1e-5f);
    g_scale_a[j] = sca;
    g_shift_a[j] = betaBN[j] - mua * sca;
}

// ---------------- combine + BN + row L2 normalize ----------------
__global__ __launch_bounds__(256) void out_paper_kernel(
    const float* __restrict__ z1, const float* __restrict__ z2,
    float* __restrict__ out, int M) {
    int gt = blockIdx.x * blockDim.x + threadIdx.x;
    int row = gt >> 5, lane = gt & 31;
    if (row >= M) return;
    float b1 = g_beta[0], b2 = g_beta[1];
    float4 v1 = *((const float4*)(z1 + (size_t)row * 128) + lane);
    float4 v2 = *((const float4*)(z2 + (size_t)row * 128) + lane);
    float4 sc = *(const float4*)&g_scale_p[lane * 4];
    float4 sh = *(const float4*)&g_shift_p[lane * 4];
    float4 y;
    y.x = (b1 * v1.x + b2 * v2.x) * sc.x + sh.x;
    y.y = (b1 * v1.y + b2 * v2.y) * sc.y + sh.y;
    y.z = (b1 * v1.z + b2 * v2.z) * sc.z + sh.z;
    y.w = (b1 * v1.w + b2 * v2.w) * sc.w + sh.w;
    float ss = y.x * y.x + y.y * y.y + y.z * y.z + y.w * y.w;
#pragma unroll
    for (int o = 16; o > 0; o >>= 1) ss += __shfl_xor_sync(0xffffffffu, ss, o);
    float inv = rsqrtf(ss + 1e-12f);
    float4 o4 = make_float4(y.x * inv, y.y * inv, y.z * inv, y.w * inv);
    *((float4*)(out + (size_t)row * 128) + lane) = o4;
}

__global__ __launch_bounds__(256) void out_author_kernel(
    const float* __restrict__ z3, float* __restrict__ out, int M) {
    int gt = blockIdx.x * blockDim.x + threadIdx.x;
    int row = gt >> 5, lane = gt & 31;
    if (row >= M) return;
    float4 v = *((const float4*)(z3 + (size_t)row * 128) + lane);
    float4 sc = *(const float4*)&g_scale_a[lane * 4];
    float4 sh = *(const float4*)&g_shift_a[lane * 4];
    float4 y;
    y.x = v.x * sc.x + sh.x;
    y.y = v.y * sc.y + sh.y;
    y.z = v.z * sc.z + sh.z;
    y.w = v.w * sc.w + sh.w;
    float ss = y.x * y.x + y.y * y.y + y.z * y.z + y.w * y.w;
#pragma unroll
    for (int o = 16; o > 0; o >>= 1) ss += __shfl_xor_sync(0xffffffffu, ss, o);
    float inv = rsqrtf(ss + 1e-12f);
    float4 o4 = make_float4(y.x * inv, y.y * inv, y.z * inv, y.w * inv);
    *((float4*)(out + (size_t)row * 128) + lane) = o4;
}

// ---------------- launch ----------------
extern "C" void kernel_launch(void* const* d_in, const int* in_sizes, int n_in,
                              void* d_out, int out_size) {
    const float* h_paper  = (const float*)d_in[0];
    const float* h_author = (const float*)d_in[1];
    const float* W1   = (const float*)d_in[2];
    const float* W2   = (const float*)d_in[3];
    const float* W3   = (const float*)d_in[4];
    const float* attW = (const float*)d_in[5];
    const float* attb = (const float*)d_in[6];
    const float* attq = (const float*)d_in[7];
    const float* gamma  = (const float*)d_in[8];
    const float* betaBN = (const float*)d_in[9];
    const int* s1 = (const int*)d_in[10];
    const int* d1 = (const int*)d_in[11];
    const int* s2 = (const int*)d_in[12];
    const int* d2 = (const int*)d_in[13];
    const int* s3 = (const int*)d_in[14];
    const int* d3 = (const int*)d_in[15];
    float* out = (float*)d_out;

    const int MP = in_sizes[0] / Dv;
    const int MA = in_sizes[1] / Dv;
    const int E  = in_sizes[10];

    float *agg1, *agg2, *agg3, *z1, *z2, *z3, *deg, *wsum;
    int2* ebuf;
    cudaGetSymbolAddress((void**)&agg1, g_agg1);
    cudaGetSymbolAddress((void**)&agg2, g_agg2);
    cudaGetSymbolAddress((void**)&agg3, g_agg3);
    cudaGetSymbolAddress((void**)&z1, g_z1);
    cudaGetSymbolAddress((void**)&z2, g_z2);
    cudaGetSymbolAddress((void**)&z3, g_z3);
    cudaGetSymbolAddress((void**)&deg, g_deg);
    cudaGetSymbolAddress((void**)&wsum, g_wsum);
    cudaGetSymbolAddress((void**)&ebuf, g_ebuf);

    // 1. zero agg/deg/stats/wsum
    {
        size_t n4 = (size_t)MP * Dv / 4;
        int blocks = (int)((n4 + 255) / 256);
        zero_kernel<<<blocks, 256>>>();
    }
    // 2. degrees (raw counts)
    degree_kernel<<<(E + 255) / 256, 256>>>(s1, d1, s2, d2, s3, d3, E);
    // 3. counting-sort offsets from raw deg_out (before rsqrt!)
    src_prefix_kernel<<<3, 1024>>>(MP);
    // 4. rsqrt degrees
    rsqrt_deg_kernel<<<(6 * 50000 + 255) / 256, 256>>>(6 * 50000);
    // 5. fill src-sorted edge lists
    {
        dim3 g((E + 255) / 256, 3);
        fill_kernel<<<g, 256>>>(s1, d1, s2, d2, s3, d3, E);
    }
    // 6. scatter over sorted edges (REDG, L1-hot gather)
    {
        int warps = (E + 3) / 4;
        int blocks = (warps * 32 + 255) / 256;
        scatter_kernel<<<blocks, 256>>>(h_author, ebuf + 0 * Emax, deg + 0 * 50000, agg1, E);
        scatter_kernel<<<blocks, 256>>>(h_paper,  ebuf + 1 * Emax, deg + 2 * 50000, agg2, E);
        scatter_kernel<<<blocks, 256>>>(h_author, ebuf + 2 * Emax, deg + 4 * 50000, agg3, E);
    }
    // 7. conv GEMMs + attention GEMMs (tf32 tensor cores)
    {
        dim3 g((MP + 127) / 128, 3);
        conv_gemm_tf32<<<g, 256>>>(agg1, agg2, agg3, W1, W2, W3,
                                   deg + 1 * 50000, deg + 3 * 50000, deg + 5 * 50000,
                                   z1, z2, z3, MP);
        dim3 ga((MP + 127) / 128, 2);
        att_gemm_tf32<<<ga, 256>>>(z1, z2, attW, attb, attq, wsum, MP);
    }
    // 8. moments, finalize, outputs
    stats_paper_kernel<<<(MP + 127) / 128, 128>>>(z1, z2, MP);
    stats_author_kernel<<<(MA + 127) / 128, 128>>>(z3, MA);
    finalize_kernel<<<1, 128>>>(gamma, betaBN, MP, MA);
    out_paper_kernel<<<(MP * 32 + 255) / 256, 256>>>(z1, z2, out, MP);
    out_author_kernel<<<(MA * 32 + 255) / 256, 256>>>(z3, out + (size_t)MP * Dv, MA);
}

// round 8
// speedup vs baseline: 1.6567x; 1.1735x over previous
#include <cuda_runtime.h>
#include <cuda_fp16.h>
#include <cstdint>

#define NPv 50000
#define NAv 50000
#define Dv  128

// ---------------- scratch ----------------
__device__ float g_agg1[(size_t)NPv * Dv];
__device__ float g_agg2[(size_t)NPv * Dv];
__device__ float g_agg3[(size_t)NAv * Dv];
__device__ float g_z1[(size_t)NPv * Dv];
__device__ float g_z2[(size_t)NPv * Dv];
__device__ float g_z3[(size_t)NAv * Dv];
__device__ __half g_h16[(size_t)(NPv + NAv) * Dv];   // [paper | author] fp16 table
__device__ float g_deg[6 * 50000];
__device__ float g_stats[7 * 128];
__device__ float g_wsum[2];
__device__ float g_beta[2];
__device__ float g_scale_p[128], g_shift_p[128];
__device__ float g_scale_a[128], g_shift_a[128];

// ---------------- tf32 helpers ----------------
__device__ __forceinline__ uint32_t cvt_tf32(float x) {
    uint32_t r;
    asm("cvt.rna.tf32.f32 %0, %1;" : "=r"(r) : "f"(x));
    return r;
}
__device__ __forceinline__ void mma_tf32(float4& d, const uint32_t a[4],
                                         uint32_t b0, uint32_t b1) {
    asm volatile(
        "mma.sync.aligned.m16n8k8.row.col.f32.tf32.tf32.f32 "
        "{%0,%1,%2,%3},{%4,%5,%6,%7},{%8,%9},{%0,%1,%2,%3};"
        : "+f"(d.x), "+f"(d.y), "+f"(d.z), "+f"(d.w)
        : "r"(a[0]), "r"(a[1]), "r"(a[2]), "r"(a[3]), "r"(b0), "r"(b1));
}

// ---------------- zero scratch ----------------
__global__ void zero_kernel() {
    size_t i = (size_t)blockIdx.x * blockDim.x + threadIdx.x;   // float4 index
    size_t n4 = (size_t)NPv * Dv / 4;
    float4 z = make_float4(0.f, 0.f, 0.f, 0.f);
    if (i < n4) {
        ((float4*)g_agg1)[i] = z;
        ((float4*)g_agg2)[i] = z;
        ((float4*)g_agg3)[i] = z;
    }
    if (i < (6 * 50000) / 4) ((float4*)g_deg)[i] = z;
    if (i < (7 * 128) / 4) ((float4*)g_stats)[i] = z;
    if (i < 2) g_wsum[i] = 0.f;
}

// ---------------- fp32 -> fp16 feature table ----------------
__global__ void h2half_kernel(const float* __restrict__ hp, const float* __restrict__ ha) {
    size_t i = (size_t)blockIdx.x * blockDim.x + threadIdx.x;   // unit = 8 elems
    const size_t n8 = (size_t)NPv * Dv / 8;
    const float* srcB;
    size_t j;
    if (i < n8) { srcB = hp; j = i; }
    else if (i < 2 * n8) { srcB = ha; j = i - n8; }
    else return;
    float4 a = ((const float4*)srcB)[2 * j];
    float4 b = ((const float4*)srcB)[2 * j + 1];
    __half2 p0 = __floats2half2_rn(a.x, a.y);
    __half2 p1 = __floats2half2_rn(a.z, a.w);
    __half2 p2 = __floats2half2_rn(b.x, b.y);
    __half2 p3 = __floats2half2_rn(b.z, b.w);
    uint4 o;
    o.x = *(uint32_t*)&p0; o.y = *(uint32_t*)&p1;
    o.z = *(uint32_t*)&p2; o.w = *(uint32_t*)&p3;
    ((uint4*)g_h16)[i] = o;
}

// ---------------- degrees ----------------
__global__ void degree_kernel(const int* __restrict__ s1, const int* __restrict__ d1,
                              const int* __restrict__ s2, const int* __restrict__ d2,
                              const int* __restrict__ s3, const int* __restrict__ d3,
                              int nE) {
    int i = blockIdx.x * blockDim.x + threadIdx.x;
    if (i >= nE) return;
    atomicAdd(&g_deg[0 * 50000 + s1[i]], 1.0f);
    atomicAdd(&g_deg[1 * 50000 + d1[i]], 1.0f);
    atomicAdd(&g_deg[2 * 50000 + s2[i]], 1.0f);
    atomicAdd(&g_deg[3 * 50000 + d2[i]], 1.0f);
    atomicAdd(&g_deg[4 * 50000 + s3[i]], 1.0f);
    atomicAdd(&g_deg[5 * 50000 + d3[i]], 1.0f);
}

__global__ void rsqrt_deg_kernel(int n) {
    int i = blockIdx.x * blockDim.x + threadIdx.x;
    if (i < n) g_deg[i] = rsqrtf(fmaxf(g_deg[i], 1.0f));
}

// ------- scatter: 4 edges/warp, fp16 gather, fp32 REDG.v4, grid.y = rel ------
__global__ __launch_bounds__(256) void scatter_kernel(
    const int* __restrict__ s1, const int* __restrict__ d1,
    const int* __restrict__ s2, const int* __restrict__ d2,
    const int* __restrict__ s3, const int* __restrict__ d3,
    int nE) {
    int rel = blockIdx.y;
    const int* src = rel == 0 ? s1 : rel == 1 ? s2 : s3;
    const int* dst = rel == 0 ? d1 : rel == 1 ? d2 : d3;
    // rel 0 gathers author, rel 1 paper, rel 2 author
    const __half* H = (rel == 1) ? g_h16 : g_h16 + (size_t)NPv * Dv;
    const float* rs_out = g_deg + (2 * rel) * 50000;
    float* agg = (rel == 0) ? g_agg1 : (rel == 1) ? g_agg2 : g_agg3;

    int warp = (blockIdx.x * blockDim.x + threadIdx.x) >> 5;
    int lane = threadIdx.x & 31;
    int e0 = warp << 2;
    if (e0 >= nE) return;

    int s[4], d[4];
#pragma unroll
    for (int i = 0; i < 4; i++) {
        int e = min(e0 + i, nE - 1);
        s[i] = __ldg(src + e);
        d[i] = __ldg(dst + e);
    }
    float sc[4];
#pragma unroll
    for (int i = 0; i < 4; i++) sc[i] = __ldg(rs_out + s[i]);
    uint2 raw[4];
#pragma unroll
    for (int i = 0; i < 4; i++)
        raw[i] = *((const uint2*)(H + (size_t)s[i] * Dv) + lane);   // 4 halves/lane

    int n = min(4, nE - e0);
#pragma unroll
    for (int i = 0; i < 4; i++) {
        if (i < n) {
            float2 f01 = __half22float2(*(const __half2*)&raw[i].x);
            float2 f23 = __half22float2(*(const __half2*)&raw[i].y);
            float c = sc[i];
            float4 u = make_float4(f01.x * c, f01.y * c, f23.x * c, f23.y * c);
            float* p = agg + (size_t)d[i] * Dv + lane * 4;
            asm volatile("red.global.add.v4.f32 [%0], {%1,%2,%3,%4};"
                         :: "l"(p), "f"(u.x), "f"(u.y), "f"(u.z), "f"(u.w) : "memory");
        }
    }
}

// ============ TF32 GEMM core: block tile 128x128, 8 warps (4m x 2n) ==========
#define GEMM_PROLOGUE()                                                        \
    __shared__ float As[128][36];                                              \
    __shared__ float Ws[32][136];                                              \
    const int tid = threadIdx.x;                                               \
    const int wid = tid >> 5, lane = tid & 31;                                 \
    const int grp = lane >> 2, tig = lane & 3;                                 \
    const int rowBase = blockIdx.x * 128;                                      \
    const int rowOff = (wid & 3) * 32;                                         \
    const int colOff = (wid >> 2) * 64;                                        \
    float4 acc[2][8];                                                          \
    _Pragma("unroll") for (int ms = 0; ms < 2; ms++)                           \
        _Pragma("unroll") for (int ns = 0; ns < 8; ns++)                       \
            acc[ms][ns] = make_float4(0.f, 0.f, 0.f, 0.f);

#define LOAD_CHUNK(kc)                                                         \
    _Pragma("unroll") for (int j = 0; j < 4; j++) {                            \
        int i = tid + 256 * j;                                                 \
        int r = i >> 3, c4 = (i & 7) << 2;                                     \
        int gr = min(rowBase + r, M - 1);                                      \
        aPre[j] = *(const float4*)(A + (size_t)gr * 128 + (kc) * 32 + c4);     \
        int k = i >> 5, w4 = (i & 31) << 2;                                    \
        wPre[j] = *(const float4*)(W + (size_t)((kc) * 32 + k) * 128 + w4);    \
    }

#define STORE_CHUNK()                                                          \
    _Pragma("unroll") for (int j = 0; j < 4; j++) {                            \
        int i = tid + 256 * j;                                                 \
        int r = i >> 3, c4 = (i & 7) << 2;                                     \
        uint4 ta;                                                              \
        ta.x = cvt_tf32(aPre[j].x); ta.y = cvt_tf32(aPre[j].y);                \
        ta.z = cvt_tf32(aPre[j].z); ta.w = cvt_tf32(aPre[j].w);                \
        *(uint4*)&As[r][c4] = ta;                                              \
        int k = i >> 5, w4 = (i & 31) << 2;                                    \
        uint4 tw;                                                              \
        tw.x = cvt_tf32(wPre[j].x); tw.y = cvt_tf32(wPre[j].y);                \
        tw.z = cvt_tf32(wPre[j].z); tw.w = cvt_tf32(wPre[j].w);                \
        *(uint4*)&Ws[k][w4] = tw;                                              \
    }

#define MMA_CHUNK()                                                            \
    _Pragma("unroll") for (int ks = 0; ks < 4; ks++) {                         \
        int k0 = ks * 8;                                                       \
        uint32_t a[2][4];                                                      \
        _Pragma("unroll") for (int ms = 0; ms < 2; ms++) {                     \
            int r = rowOff + ms * 16 + grp;                                    \
            a[ms][0] = __float_as_uint(As[r][k0 + tig]);                       \
            a[ms][1] = __float_as_uint(As[r + 8][k0 + tig]);                   \
            a[ms][2] = __float_as_uint(As[r][k0 + tig + 4]);                   \
            a[ms][3] = __float_as_uint(As[r + 8][k0 + tig + 4]);               \
        }                                                                      \
        _Pragma("unroll") for (int ns = 0; ns < 8; ns++) {                     \
            int cn = colOff + ns * 8 + grp;                                    \
            uint32_t b0 = __float_as_uint(Ws[k0 + tig][cn]);                   \
            uint32_t b1 = __float_as_uint(Ws[k0 + tig + 4][cn]);               \
            mma_tf32(acc[0][ns], a[0], b0, b1);                                \
            mma_tf32(acc[1][ns], a[1], b0, b1);                                \
        }                                                                      \
    }

#define GEMM_MAINLOOP()                                                        \
    float4 aPre[4], wPre[4];                                                   \
    LOAD_CHUNK(0)                                                              \
    _Pragma("unroll") for (int kc = 0; kc < 4; kc++) {                         \
        if (kc > 0) __syncthreads();                                           \
        STORE_CHUNK()                                                          \
        __syncthreads();                                                       \
        if (kc < 3) { LOAD_CHUNK(kc + 1) }                                     \
        MMA_CHUNK()                                                            \
    }

__global__ __launch_bounds__(256, 2) void conv_gemm_tf32(
    const float* __restrict__ A1, const float* __restrict__ A2, const float* __restrict__ A3,
    const float* __restrict__ W1, const float* __restrict__ W2, const float* __restrict__ W3,
    const float* __restrict__ rs1, const float* __restrict__ rs2, const float* __restrict__ rs3,
    float* __restrict__ C1, float* __restrict__ C2, float* __restrict__ C3, int M) {
    const int rel = blockIdx.y;
    const float* A = rel == 0 ? A1 : rel == 1 ? A2 : A3;
    const float* W = rel == 0 ? W1 : rel == 1 ? W2 : W3;
    const float* rs = rel == 0 ? rs1 : rel == 1 ? rs2 : rs3;
    float* C = rel == 0 ? C1 : rel == 1 ? C2 : C3;

    GEMM_PROLOGUE()
    GEMM_MAINLOOP()

#pragma unroll
    for (int ms = 0; ms < 2; ms++) {
        int rA = rowBase + rowOff + ms * 16 + grp;
        int rB = rA + 8;
        float sA = (rA < M) ? rs[rA] : 0.f;
        float sB = (rB < M) ? rs[rB] : 0.f;
#pragma unroll
        for (int ns = 0; ns < 8; ns++) {
            int cC = colOff + ns * 8 + 2 * tig;
            if (rA < M) {
                float2 o = make_float2(acc[ms][ns].x * sA, acc[ms][ns].y * sA);
                *(float2*)(C + (size_t)rA * 128 + cC) = o;
            }
            if (rB < M) {
                float2 o = make_float2(acc[ms][ns].z * sB, acc[ms][ns].w * sB);
                *(float2*)(C + (size_t)rB * 128 + cC) = o;
            }
        }
    }
}

__global__ __launch_bounds__(256, 2) void att_gemm_tf32(
    const float* __restrict__ Z1, const float* __restrict__ Z2,
    const float* __restrict__ W,
    const float* __restrict__ bb, const float* __restrict__ qq,
    float* __restrict__ wsum, int M) {
    const float* A = blockIdx.y == 0 ? Z1 : Z2;

    GEMM_PROLOGUE()
    GEMM_MAINLOOP()

    float p = 0.f;
#pragma unroll
    for (int ms = 0; ms < 2; ms++) {
        int rA = rowBase + rowOff + ms * 16 + grp;
        int rB = rA + 8;
#pragma unroll
        for (int ns = 0; ns < 8; ns++) {
            int cC = colOff + ns * 8 + 2 * tig;
            float b0v = __ldg(bb + cC), b1v = __ldg(bb + cC + 1);
            float q0v = __ldg(qq + cC), q1v = __ldg(qq + cC + 1);
            if (rA < M)
                p += tanhf(acc[ms][ns].x + b0v) * q0v + tanhf(acc[ms][ns].y + b1v) * q1v;
            if (rB < M)
                p += tanhf(acc[ms][ns].z + b0v) * q0v + tanhf(acc[ms][ns].w + b1v) * q1v;
        }
    }
#pragma unroll
    for (int o = 16; o > 0; o >>= 1) p += __shfl_xor_sync(0xffffffffu, p, o);
    if (lane == 0) atomicAdd(wsum + blockIdx.y, p);
}

// ---------------- column moments (merged: y=0 paper, y=1 author) -------------
__global__ __launch_bounds__(128) void stats_kernel(
    const float* __restrict__ z1, const float* __restrict__ z2,
    const float* __restrict__ z3, int MP, int MA) {
    int c = threadIdx.x;
    if (blockIdx.y == 0) {
        int r0 = blockIdx.x * 128;
        int r1 = min(r0 + 128, MP);
        if (r0 >= MP) return;
        float s1 = 0.f, s2 = 0.f, q1 = 0.f, q2 = 0.f, cx = 0.f;
        for (int r = r0; r < r1; r++) {
            float v1 = z1[(size_t)r * 128 + c];
            float v2 = z2[(size_t)r * 128 + c];
            s1 += v1; s2 += v2; q1 += v1 * v1; q2 += v2 * v2; cx += v1 * v2;
        }
        atomicAdd(&g_stats[0 * 128 + c], s1);
        atomicAdd(&g_stats[1 * 128 + c], s2);
        atomicAdd(&g_stats[2 * 128 + c], q1);
        atomicAdd(&g_stats[3 * 128 + c], q2);
        atomicAdd(&g_stats[4 * 128 + c], cx);
    } else {
        int r0 = blockIdx.x * 128;
        int r1 = min(r0 + 128, MA);
        if (r0 >= MA) return;
        float s3 = 0.f, q3 = 0.f;
        for (int r = r0; r < r1; r++) {
            float v = z3[(size_t)r * 128 + c];
            s3 += v; q3 += v * v;
        }
        atomicAdd(&g_stats[5 * 128 + c], s3);
        atomicAdd(&g_stats[6 * 128 + c], q3);
    }
}

// ---------------- finalize ----------------
__global__ void finalize_kernel(const float* __restrict__ gamma, const float* __restrict__ betaBN,
                                int MP, int MA) {
    int j = threadIdx.x;
    float w1 = g_wsum[0] / (float)MP;
    float w2 = g_wsum[1] / (float)MP;
    float m = fmaxf(w1, w2);
    float e1 = expf(w1 - m), e2 = expf(w2 - m);
    float b1 = e1 / (e1 + e2), b2 = e2 / (e1 + e2);
    if (j == 0) { g_beta[0] = b1; g_beta[1] = b2; }

    float S1 = g_stats[0 * 128 + j], S2 = g_stats[1 * 128 + j];
    float Q1 = g_stats[2 * 128 + j], Q2 = g_stats[3 * 128 + j];
    float CX = g_stats[4 * 128 + j];
    float S3 = g_stats[5 * 128 + j], Q3 = g_stats[6 * 128 + j];

    float invMP = 1.0f / (float)MP;
    float mu = (b1 * S1 + b2 * S2) * invMP;
    float ex2 = (b1 * b1 * Q1 + 2.f * b1 * b2 * CX + b2 * b2 * Q2) * invMP;
    float var = ex2 - mu * mu;
    float sc = gamma[j] * rsqrtf(var + 1e-5f);
    g_scale_p[j] = sc;
    g_shift_p[j] = betaBN[j] - mu * sc;

    float invMA = 1.0f / (float)MA;
    float mua = S3 * invMA;
    float vara = Q3 * invMA - mua * mua;
    float sca = gamma[j] * rsqrtf(vara + 1e-5f);
    g_scale_a[j] = sca;
    g_shift_a[j] = betaBN[j] - mua * sca;
}

// -------- combine + BN + row L2 normalize (merged: y=0 paper, y=1 author) ----
__global__ __launch_bounds__(256) void out_kernel(
    const float* __restrict__ z1, const float* __restrict__ z2,
    const float* __restrict__ z3, float* __restrict__ out, int MP, int MA) {
    int gt = blockIdx.x * blockDim.x + threadIdx.x;
    int row = gt >> 5, lane = gt & 31;
    float4 y;
    float* o;
    if (blockIdx.y == 0) {
        if (row >= MP) return;
        float b1 = g_beta[0], b2 = g_beta[1];
        float4 v1 = *((const float4*)(z1 + (size_t)row * 128) + lane);
        float4 v2 = *((const float4*)(z2 + (size_t)row * 128) + lane);
        float4 sc = *(const float4*)&g_scale_p[lane * 4];
        float4 sh = *(const float4*)&g_shift_p[lane * 4];
        y.x = (b1 * v1.x + b2 * v2.x) * sc.x + sh.x;
        y.y = (b1 * v1.y + b2 * v2.y) * sc.y + sh.y;
        y.z = (b1 * v1.z + b2 * v2.z) * sc.z + sh.z;
        y.w = (b1 * v1.w + b2 * v2.w) * sc.w + sh.w;
        o = out + (size_t)row * 128;
    } else {
        if (row >= MA) return;
        float4 v = *((const float4*)(z3 + (size_t)row * 128) + lane);
        float4 sc = *(const float4*)&g_scale_a[lane * 4];
        float4 sh = *(const float4*)&g_shift_a[lane * 4];
        y.x = v.x * sc.x + sh.x;
        y.y = v.y * sc.y + sh.y;
        y.z = v.z * sc.z + sh.z;
        y.w = v.w * sc.w + sh.w;
        o = out + (size_t)(MP + row) * 128;
    }
    float ss = y.x * y.x + y.y * y.y + y.z * y.z + y.w * y.w;
#pragma unroll
    for (int off = 16; off > 0; off >>= 1) ss += __shfl_xor_sync(0xffffffffu, ss, off);
    float inv = rsqrtf(ss + 1e-12f);
    ((float4*)o)[lane] = make_float4(y.x * inv, y.y * inv, y.z * inv, y.w * inv);
}

// ---------------- launch ----------------
extern "C" void kernel_launch(void* const* d_in, const int* in_sizes, int n_in,
                              void* d_out, int out_size) {
    const float* h_paper  = (const float*)d_in[0];
    const float* h_author = (const float*)d_in[1];
    const float* W1   = (const float*)d_in[2];
    const float* W2   = (const float*)d_in[3];
    const float* W3   = (const float*)d_in[4];
    const float* attW = (const float*)d_in[5];
    const float* attb = (const float*)d_in[6];
    const float* attq = (const float*)d_in[7];
    const float* gamma  = (const float*)d_in[8];
    const float* betaBN = (const float*)d_in[9];
    const int* s1 = (const int*)d_in[10];
    const int* d1 = (const int*)d_in[11];
    const int* s2 = (const int*)d_in[12];
    const int* d2 = (const int*)d_in[13];
    const int* s3 = (const int*)d_in[14];
    const int* d3 = (const int*)d_in[15];
    float* out = (float*)d_out;

    const int MP = in_sizes[0] / Dv;
    const int MA = in_sizes[1] / Dv;
    const int E  = in_sizes[10];

    float *agg1, *agg2, *agg3, *z1, *z2, *z3, *deg, *wsum;
    cudaGetSymbolAddress((void**)&agg1, g_agg1);
    cudaGetSymbolAddress((void**)&agg2, g_agg2);
    cudaGetSymbolAddress((void**)&agg3, g_agg3);
    cudaGetSymbolAddress((void**)&z1, g_z1);
    cudaGetSymbolAddress((void**)&z2, g_z2);
    cudaGetSymbolAddress((void**)&z3, g_z3);
    cudaGetSymbolAddress((void**)&deg, g_deg);
    cudaGetSymbolAddress((void**)&wsum, g_wsum);

    // 1. zero agg/deg/stats/wsum
    {
        size_t n4 = (size_t)MP * Dv / 4;
        int blocks = (int)((n4 + 255) / 256);
        zero_kernel<<<blocks, 256>>>();
    }
    // 2. fp16 feature table
    {
        size_t n8 = (size_t)(MP + MA) * Dv / 8;
        h2half_kernel<<<(int)((n8 + 255) / 256), 256>>>(h_paper, h_author);
    }
    // 3. degrees + rsqrt
    degree_kernel<<<(E + 255) / 256, 256>>>(s1, d1, s2, d2, s3, d3, E);
    rsqrt_deg_kernel<<<(6 * 50000 + 255) / 256, 256>>>(6 * 50000);
    // 4. scatter: all 3 relations in one launch, fp16 gather + fp32 REDG
    {
        int warps = (E + 3) / 4;
        dim3 g((warps * 32 + 255) / 256, 3);
        scatter_kernel<<<g, 256>>>(s1, d1, s2, d2, s3, d3, E);
    }
    // 5. conv GEMMs + attention GEMMs (tf32 tensor cores)
    {
        dim3 g((MP + 127) / 128, 3);
        conv_gemm_tf32<<<g, 256>>>(agg1, agg2, agg3, W1, W2, W3,
                                   deg + 1 * 50000, deg + 3 * 50000, deg + 5 * 50000,
                                   z1, z2, z3, MP);
        dim3 ga((MP + 127) / 128, 2);
        att_gemm_tf32<<<ga, 256>>>(z1, z2, attW, attb, attq, wsum, MP);
    }
    // 6. moments, finalize, outputs
    {
        dim3 gs((MP + 127) / 128, 2);
        stats_kernel<<<gs, 128>>>(z1, z2, z3, MP, MA);
    }
    finalize_kernel<<<1, 128>>>(gamma, betaBN, MP, MA);
    {
        dim3 go((MP * 32 + 255) / 256, 2);
        out_kernel<<<go, 256>>>(z1, z2, z3, out, MP, MA);
    }
}